// round 6
// baseline (speedup 1.0000x reference)
#include <cuda_runtime.h>
#include <math.h>

#define NG   8192
#define SS   64
#define DD   128
#define HH   256
#define KK   8
#define GPB  8
#define EPSV 0.01f

#define OFF_MIX   (NG * DD)
#define OFF_SCALE (OFF_MIX + NG * KK)
#define OFF_ALPHA (OFF_SCALE + NG)
#define OFF_BETA  (OFF_ALPHA + NG)

// ---- packed f32x2 helpers (sm_103a) ----------------------------------------
__device__ __forceinline__ double add2(double a, double b) {
    double r; asm("add.rn.f32x2 %0,%1,%2;" : "=d"(r) : "d"(a), "d"(b)); return r;
}
__device__ __forceinline__ double fma2(double a, double b, double c) {
    double r; asm("fma.rn.f32x2 %0,%1,%2,%3;" : "=d"(r) : "d"(a), "d"(b), "d"(c)); return r;
}
__device__ __forceinline__ double pack2(float lo, float hi) {
    double r; asm("mov.b64 %0,{%1,%2};" : "=d"(r) : "f"(lo), "f"(hi)); return r;
}
__device__ __forceinline__ float2 unpack2(double v) {
    float2 r; asm("mov.b64 {%0,%1},%2;" : "=f"(r.x), "=f"(r.y) : "d"(v)); return r;
}
__device__ __forceinline__ float softplus_f(float v) {
    return v > 20.0f ? v : log1pf(expf(v));
}

__global__ __launch_bounds__(256, 4)
void fused_kernel(
    const float* __restrict__ x,
    const float* __restrict__ y,
    const float* __restrict__ anchor_x,
    const float* __restrict__ anchor_y,
    const float* __restrict__ W1,
    const float* __restrict__ b1,
    const float* __restrict__ W2,
    const float* __restrict__ b2,
    float* __restrict__ out)
{
    __shared__ double2 rep_p[GPB / 2][DD / 2];   // pair-interleaved rep, 4 KB
    __shared__ float   h_s[GPB][HH + 1];         // 8.2 KB
    __shared__ float   w2t[KK + 2][HH];          // 10 KB

    const int tid = threadIdx.x;
    const int w   = tid >> 5;
    const int l   = tid & 31;
    const int g   = blockIdx.x * GPB + w;

    // stage transposed W2 early (L2-hot after first blocks; hides under stats)
    #pragma unroll
    for (int i = tid; i < HH * (KK + 2); i += 256) {
        int j = i / (KK + 2);
        int k = i - j * (KK + 2);
        w2t[k][j] = W2[i];
    }

    // ---------------- Phase 1: per-group statistics (1 warp / group) ----------
    {
        const float4* xg = reinterpret_cast<const float4*>(x + (size_t)g * SS * DD) + l;
        const float*  yg = y + (size_t)g * SS;
        float4 a4 = reinterpret_cast<const float4*>(anchor_x + (size_t)g * DD)[l];
        const float ayv = anchor_y[g];

        const double na_lo = pack2(-a4.x, -a4.y);
        const double na_hi = pack2(-a4.z, -a4.w);

        double sx_lo = 0.0, sx_hi = 0.0;
        double sxy_lo = 0.0, sxy_hi = 0.0;
        double sxx2 = 0.0;
        float  sy = 0.f;

        float4 c0, c1, c2, c3;
        float  yv0, yv1, yv2, yv3;
        c0 = xg[0 * (DD / 4)]; c1 = xg[1 * (DD / 4)];
        c2 = xg[2 * (DD / 4)]; c3 = xg[3 * (DD / 4)];
        yv0 = yg[0]; yv1 = yg[1]; yv2 = yg[2]; yv3 = yg[3];

        #pragma unroll
        for (int b = 0; b < SS / 4; ++b) {
            float4 n0, n1, n2, n3;
            float  yn0, yn1, yn2, yn3;
            if (b < SS / 4 - 1) {
                const int base = (b + 1) * 4;
                n0 = xg[(base + 0) * (DD / 4)];
                n1 = xg[(base + 1) * (DD / 4)];
                n2 = xg[(base + 2) * (DD / 4)];
                n3 = xg[(base + 3) * (DD / 4)];
                yn0 = yg[base + 0]; yn1 = yg[base + 1];
                yn2 = yg[base + 2]; yn3 = yg[base + 3];
            }
            {
                float4 cc[4] = {c0, c1, c2, c3};
                float  yy[4] = {yv0, yv1, yv2, yv3};
                #pragma unroll
                for (int k = 0; k < 4; ++k) {
                    double2 xd = *reinterpret_cast<double2*>(&cc[k]);
                    float yr = yy[k] - ayv;
                    double yr2 = pack2(yr, yr);
                    double xr_lo = add2(xd.x, na_lo);
                    double xr_hi = add2(xd.y, na_hi);
                    sx_lo  = add2(sx_lo, xr_lo);
                    sx_hi  = add2(sx_hi, xr_hi);
                    sxy_lo = fma2(xr_lo, yr2, sxy_lo);
                    sxy_hi = fma2(xr_hi, yr2, sxy_hi);
                    sxx2   = fma2(xr_lo, xr_lo, sxx2);
                    sxx2   = fma2(xr_hi, xr_hi, sxx2);
                    sy += yr;
                }
            }
            c0 = n0; c1 = n1; c2 = n2; c3 = n3;
            yv0 = yn0; yv1 = yn1; yv2 = yn2; yv3 = yn3;
        }

        float2 sxxp = unpack2(sxx2);
        float sxx = sxxp.x + sxxp.y;
        float2 sxl = unpack2(sx_lo),  sxh = unpack2(sx_hi);
        float2 syl = unpack2(sxy_lo), syh = unpack2(sxy_hi);
        float tot = sxl.x + sxl.y + sxh.x + sxh.y;

        #pragma unroll
        for (int o = 16; o > 0; o >>= 1) {
            sxx += __shfl_xor_sync(0xFFFFFFFFu, sxx, o);
            tot += __shfl_xor_sync(0xFFFFFFFFu, tot, o);
        }

        const float nD      = (float)(SS * DD);
        const float var     = (sxx - tot * tot / nD) / (nD - 1.0f);
        const float inv_var = 1.0f / var;
        const float c       = sy / (float)SS;
        const float inv_nm1 = 1.0f / (float)(SS - 1);

        float4 rep;
        rep.x = (syl.x - sxl.x * c) * inv_nm1 * inv_var;
        rep.y = (syl.y - sxl.y * c) * inv_nm1 * inv_var;
        rep.z = (syh.x - sxh.x * c) * inv_nm1 * inv_var;
        rep.w = (syh.y - sxh.y * c) * inv_nm1 * inv_var;

        reinterpret_cast<float4*>(out + (size_t)g * DD)[l] = rep;

        // pair-interleaved smem store: lane value for group w, dims 4l..4l+3
        {
            const int p   = w >> 1;
            const int sel = w & 1;
            float* base = reinterpret_cast<float*>(&rep_p[p][0]);
            base[2 * (4 * l + 0) + sel] = rep.x;
            base[2 * (4 * l + 1) + sel] = rep.y;
            base[2 * (4 * l + 2) + sel] = rep.z;
            base[2 * (4 * l + 3) + sel] = rep.w;
        }
    }
    __syncthreads();

    // ---------------- Phase 2a: layer 1, thread = hidden unit j ---------------
    {
        const int j = tid;                         // 0..255
        const float bj = b1[j];

        double acc[GPB / 2];
        #pragma unroll
        for (int p = 0; p < GPB / 2; ++p) acc[p] = pack2(bj, bj);

        #pragma unroll 4
        for (int d = 0; d < DD; d += 2) {
            float w0 = W1[(d + 0) * HH + j];
            float w1v = W1[(d + 1) * HH + j];
            double wd0 = pack2(w0, w0);
            double wd1 = pack2(w1v, w1v);
            #pragma unroll
            for (int p = 0; p < GPB / 2; ++p) {
                double2 rp = rep_p[p][d >> 1];     // broadcast LDS.128
                acc[p] = fma2(rp.x, wd0, acc[p]);
                acc[p] = fma2(rp.y, wd1, acc[p]);
            }
        }

        #pragma unroll
        for (int p = 0; p < GPB / 2; ++p) {
            float2 hv = unpack2(acc[p]);
            h_s[2 * p + 0][j] = tanhf(hv.x);
            h_s[2 * p + 1][j] = tanhf(hv.y);
        }
    }
    __syncthreads();

    // ---------------- Phase 2b + heads: one warp per group --------------------
    {
        const int gl = blockIdx.x * GPB + w;

        float acc[KK + 2];
        #pragma unroll
        for (int k = 0; k < KK + 2; ++k) acc[k] = 0.f;

        #pragma unroll
        for (int t = 0; t < HH / 32; ++t) {
            const int j = 32 * t + l;
            const float hv = h_s[w][j];
            #pragma unroll
            for (int k = 0; k < KK + 2; ++k)
                acc[k] = fmaf(hv, w2t[k][j], acc[k]);
        }
        #pragma unroll
        for (int k = 0; k < KK + 2; ++k) {
            #pragma unroll
            for (int o = 16; o > 0; o >>= 1)
                acc[k] += __shfl_xor_sync(0xFFFFFFFFu, acc[k], o);
        }

        if (l == 0) {
            float o0 = acc[0] + b2[0];
            float o1 = acc[1] + b2[1];
            float alpha = softplus_f(o0) * (1.0f - EPSV) + EPSV;
            float beta  = softplus_f(o1) * (1.0f - EPSV) + EPSV;

            float ok[KK];
            float m = -INFINITY;
            #pragma unroll
            for (int k = 0; k < KK; ++k) {
                ok[k] = acc[2 + k] + b2[2 + k];
                m = fmaxf(m, ok[k]);
            }
            float s = 0.f;
            #pragma unroll
            for (int k = 0; k < KK; ++k) { ok[k] = expf(ok[k] - m); s += ok[k]; }
            float inv = 1.0f / s;
            #pragma unroll
            for (int k = 0; k < KK; ++k)
                out[OFF_MIX + (size_t)gl * KK + k] = ok[k] * inv;

            out[OFF_SCALE + gl] = sqrtf(beta / alpha);
            out[OFF_ALPHA + gl] = alpha;
            out[OFF_BETA  + gl] = beta;
        }
    }
}

extern "C" void kernel_launch(void* const* d_in, const int* in_sizes, int n_in,
                              void* d_out, int out_size) {
    // inputs (metadata order): index, x, y, anchor_x, anchor_y, W1, b1, W2, b2
    const float* x        = (const float*)d_in[1];
    const float* y        = (const float*)d_in[2];
    const float* anchor_x = (const float*)d_in[3];
    const float* anchor_y = (const float*)d_in[4];
    const float* W1       = (const float*)d_in[5];
    const float* b1       = (const float*)d_in[6];
    const float* W2       = (const float*)d_in[7];
    const float* b2       = (const float*)d_in[8];
    float* out            = (float*)d_out;

    fused_kernel<<<NG / GPB, 256>>>(x, y, anchor_x, anchor_y,
                                    W1, b1, W2, b2, out);
}

// round 7
// speedup vs baseline: 1.1934x; 1.1934x over previous
#include <cuda_runtime.h>
#include <math.h>

#define NG   8192
#define SS   64
#define DD   128
#define HH   256
#define KK   8
#define GPB  8
#define NBATCH (NG / GPB)          // 1024
#define GRID   296                 // 2 blocks per SM on 148 SMs
#define EPSV 0.01f

#define OFF_MIX   (NG * DD)
#define OFF_SCALE (OFF_MIX + NG * KK)
#define OFF_ALPHA (OFF_SCALE + NG)
#define OFF_BETA  (OFF_ALPHA + NG)

// named barrier ids: 1,2 = EMPTY[p], 3,4 = FULL[p], 5 = consumer-local
#define BAR_EMPTY(p) (1 + (p))
#define BAR_FULL(p)  (3 + (p))
#define BAR_CONS     5

__device__ __forceinline__ void bar_sync(int id, int cnt) {
    asm volatile("bar.sync %0, %1;" :: "r"(id), "r"(cnt) : "memory");
}
__device__ __forceinline__ void bar_arrive(int id, int cnt) {
    asm volatile("bar.arrive %0, %1;" :: "r"(id), "r"(cnt) : "memory");
}

// ---- packed f32x2 helpers (sm_103a) ----------------------------------------
__device__ __forceinline__ double add2(double a, double b) {
    double r; asm("add.rn.f32x2 %0,%1,%2;" : "=d"(r) : "d"(a), "d"(b)); return r;
}
__device__ __forceinline__ double fma2(double a, double b, double c) {
    double r; asm("fma.rn.f32x2 %0,%1,%2,%3;" : "=d"(r) : "d"(a), "d"(b), "d"(c)); return r;
}
__device__ __forceinline__ double pack2(float lo, float hi) {
    double r; asm("mov.b64 %0,{%1,%2};" : "=d"(r) : "f"(lo), "f"(hi)); return r;
}
__device__ __forceinline__ float2 unpack2(double v) {
    float2 r; asm("mov.b64 {%0,%1},%2;" : "=f"(r.x), "=f"(r.y) : "d"(v)); return r;
}
__device__ __forceinline__ float softplus_f(float v) {
    return v > 20.0f ? v : log1pf(expf(v));
}

__global__ __launch_bounds__(512, 2)
void pipeline_kernel(
    const float* __restrict__ x,
    const float* __restrict__ y,
    const float* __restrict__ anchor_x,
    const float* __restrict__ anchor_y,
    const float* __restrict__ W1,
    const float* __restrict__ b1,
    const float* __restrict__ W2,
    const float* __restrict__ b2,
    float* __restrict__ out)
{
    __shared__ double2 rep_buf[2][GPB / 2][DD / 2];  // double-buffered rep, 8 KB
    __shared__ float   h_s[GPB][HH + 1];             // 8.2 KB (consumer-private)
    __shared__ float   w2t[KK + 2][HH];              // 10 KB

    const int tid = threadIdx.x;
    const int wid = tid >> 5;
    const int l   = tid & 31;
    const bool producer = (wid < 8);

    if (!producer) {
        // consumers stage transposed W2 once (ordered by first BAR_CONS sync)
        for (int i = tid - 256; i < HH * (KK + 2); i += 256) {
            int j = i / (KK + 2);
            int k = i - j * (KK + 2);
            w2t[k][j] = W2[i];
        }
    }

    int ib = 0;
    for (int B = blockIdx.x; B < NBATCH; B += GRID, ++ib) {
        const int p = ib & 1;

        if (producer) {
            // ================= PRODUCER: stats for group g =====================
            const int w = wid;
            const int g = B * GPB + w;

            const float4* xg = reinterpret_cast<const float4*>(x + (size_t)g * SS * DD) + l;
            const float*  yg = y + (size_t)g * SS;
            float4 a4 = reinterpret_cast<const float4*>(anchor_x + (size_t)g * DD)[l];
            const float ayv = anchor_y[g];

            const double na_lo = pack2(-a4.x, -a4.y);
            const double na_hi = pack2(-a4.z, -a4.w);

            double sx_lo = 0.0, sx_hi = 0.0;
            double sxy_lo = 0.0, sxy_hi = 0.0;
            double sxx2 = 0.0;
            float  sy = 0.f;

            float4 c0, c1, c2, c3;
            float  yv0, yv1, yv2, yv3;
            c0 = xg[0 * (DD / 4)]; c1 = xg[1 * (DD / 4)];
            c2 = xg[2 * (DD / 4)]; c3 = xg[3 * (DD / 4)];
            yv0 = yg[0]; yv1 = yg[1]; yv2 = yg[2]; yv3 = yg[3];

            #pragma unroll
            for (int b = 0; b < SS / 4; ++b) {
                float4 n0, n1, n2, n3;
                float  yn0, yn1, yn2, yn3;
                if (b < SS / 4 - 1) {
                    const int base = (b + 1) * 4;
                    n0 = xg[(base + 0) * (DD / 4)];
                    n1 = xg[(base + 1) * (DD / 4)];
                    n2 = xg[(base + 2) * (DD / 4)];
                    n3 = xg[(base + 3) * (DD / 4)];
                    yn0 = yg[base + 0]; yn1 = yg[base + 1];
                    yn2 = yg[base + 2]; yn3 = yg[base + 3];
                }
                {
                    float4 cc[4] = {c0, c1, c2, c3};
                    float  yy[4] = {yv0, yv1, yv2, yv3};
                    #pragma unroll
                    for (int k = 0; k < 4; ++k) {
                        double2 xd = *reinterpret_cast<double2*>(&cc[k]);
                        float yr = yy[k] - ayv;
                        double yr2 = pack2(yr, yr);
                        double xr_lo = add2(xd.x, na_lo);
                        double xr_hi = add2(xd.y, na_hi);
                        sx_lo  = add2(sx_lo, xr_lo);
                        sx_hi  = add2(sx_hi, xr_hi);
                        sxy_lo = fma2(xr_lo, yr2, sxy_lo);
                        sxy_hi = fma2(xr_hi, yr2, sxy_hi);
                        sxx2   = fma2(xr_lo, xr_lo, sxx2);
                        sxx2   = fma2(xr_hi, xr_hi, sxx2);
                        sy += yr;
                    }
                }
                c0 = n0; c1 = n1; c2 = n2; c3 = n3;
                yv0 = yn0; yv1 = yn1; yv2 = yn2; yv3 = yn3;
            }

            float2 sxxp = unpack2(sxx2);
            float sxx = sxxp.x + sxxp.y;
            float2 sxl = unpack2(sx_lo),  sxh = unpack2(sx_hi);
            float2 syl = unpack2(sxy_lo), syh = unpack2(sxy_hi);
            float tot = sxl.x + sxl.y + sxh.x + sxh.y;

            #pragma unroll
            for (int o = 16; o > 0; o >>= 1) {
                sxx += __shfl_xor_sync(0xFFFFFFFFu, sxx, o);
                tot += __shfl_xor_sync(0xFFFFFFFFu, tot, o);
            }

            const float nD      = (float)(SS * DD);
            const float var     = (sxx - tot * tot / nD) / (nD - 1.0f);
            const float inv_var = 1.0f / var;
            const float c       = sy / (float)SS;
            const float inv_nm1 = 1.0f / (float)(SS - 1);

            float4 rep;
            rep.x = (syl.x - sxl.x * c) * inv_nm1 * inv_var;
            rep.y = (syl.y - sxl.y * c) * inv_nm1 * inv_var;
            rep.z = (syh.x - sxh.x * c) * inv_nm1 * inv_var;
            rep.w = (syh.y - sxh.y * c) * inv_nm1 * inv_var;

            reinterpret_cast<float4*>(out + (size_t)g * DD)[l] = rep;

            // wait for buffer p to be free (first two batches: free by construction)
            if (ib >= 2) bar_sync(BAR_EMPTY(p), 512);

            // pair-interleaved smem store
            {
                const int pp  = w >> 1;
                const int sel = w & 1;
                float* base = reinterpret_cast<float*>(&rep_buf[p][pp][0]);
                base[2 * (4 * l + 0) + sel] = rep.x;
                base[2 * (4 * l + 1) + sel] = rep.y;
                base[2 * (4 * l + 2) + sel] = rep.z;
                base[2 * (4 * l + 3) + sel] = rep.w;
            }
            asm volatile("membar.cta;" ::: "memory");
            bar_arrive(BAR_FULL(p), 512);
        } else {
            // ================= CONSUMER: MLP for batch B =======================
            bar_sync(BAR_FULL(p), 512);      // wait for rep_buf[p]

            // layer 1: thread = hidden unit j (0..255), 4 packed group-pairs
            const int j = tid - 256;
            {
                const float bj = b1[j];
                double acc[GPB / 2];
                #pragma unroll
                for (int pp = 0; pp < GPB / 2; ++pp) acc[pp] = pack2(bj, bj);

                #pragma unroll 4
                for (int d = 0; d < DD; d += 2) {
                    float w0  = W1[(d + 0) * HH + j];
                    float w1v = W1[(d + 1) * HH + j];
                    double wd0 = pack2(w0, w0);
                    double wd1 = pack2(w1v, w1v);
                    #pragma unroll
                    for (int pp = 0; pp < GPB / 2; ++pp) {
                        double2 rp = rep_buf[p][pp][d >> 1];   // broadcast LDS.128
                        acc[pp] = fma2(rp.x, wd0, acc[pp]);
                        acc[pp] = fma2(rp.y, wd1, acc[pp]);
                    }
                }
                #pragma unroll
                for (int pp = 0; pp < GPB / 2; ++pp) {
                    float2 hv = unpack2(acc[pp]);
                    h_s[2 * pp + 0][j] = tanhf(hv.x);
                    h_s[2 * pp + 1][j] = tanhf(hv.y);
                }
            }
            bar_sync(BAR_CONS, 256);         // h_s complete; rep reads drained
            bar_arrive(BAR_EMPTY(p), 512);   // release buffer p to producers

            // layer 2 + heads: one consumer warp per group
            {
                const int w  = wid - 8;
                const int gl = B * GPB + w;

                float acc[KK + 2];
                #pragma unroll
                for (int k = 0; k < KK + 2; ++k) acc[k] = 0.f;

                #pragma unroll
                for (int t = 0; t < HH / 32; ++t) {
                    const int jj = 32 * t + l;
                    const float hv = h_s[w][jj];
                    #pragma unroll
                    for (int k = 0; k < KK + 2; ++k)
                        acc[k] = fmaf(hv, w2t[k][jj], acc[k]);
                }
                #pragma unroll
                for (int k = 0; k < KK + 2; ++k) {
                    #pragma unroll
                    for (int o = 16; o > 0; o >>= 1)
                        acc[k] += __shfl_xor_sync(0xFFFFFFFFu, acc[k], o);
                }

                if (l == 0) {
                    float o0 = acc[0] + b2[0];
                    float o1 = acc[1] + b2[1];
                    float alpha = softplus_f(o0) * (1.0f - EPSV) + EPSV;
                    float beta  = softplus_f(o1) * (1.0f - EPSV) + EPSV;

                    float ok[KK];
                    float m = -INFINITY;
                    #pragma unroll
                    for (int k = 0; k < KK; ++k) {
                        ok[k] = acc[2 + k] + b2[2 + k];
                        m = fmaxf(m, ok[k]);
                    }
                    float s = 0.f;
                    #pragma unroll
                    for (int k = 0; k < KK; ++k) { ok[k] = expf(ok[k] - m); s += ok[k]; }
                    float inv = 1.0f / s;
                    #pragma unroll
                    for (int k = 0; k < KK; ++k)
                        out[OFF_MIX + (size_t)gl * KK + k] = ok[k] * inv;

                    out[OFF_SCALE + gl] = sqrtf(beta / alpha);
                    out[OFF_ALPHA + gl] = alpha;
                    out[OFF_BETA  + gl] = beta;
                }
            }
        }
    }
}

extern "C" void kernel_launch(void* const* d_in, const int* in_sizes, int n_in,
                              void* d_out, int out_size) {
    // inputs (metadata order): index, x, y, anchor_x, anchor_y, W1, b1, W2, b2
    const float* x        = (const float*)d_in[1];
    const float* y        = (const float*)d_in[2];
    const float* anchor_x = (const float*)d_in[3];
    const float* anchor_y = (const float*)d_in[4];
    const float* W1       = (const float*)d_in[5];
    const float* b1       = (const float*)d_in[6];
    const float* W2       = (const float*)d_in[7];
    const float* b2       = (const float*)d_in[8];
    float* out            = (float*)d_out;

    pipeline_kernel<<<GRID, 512>>>(x, y, anchor_x, anchor_y,
                                   W1, b1, W2, b2, out);
}